// round 10
// baseline (speedup 1.0000x reference)
#include <cuda_runtime.h>
#include <cstdint>

// YOLOv7 head post-process — R10: R9 with the asm constraint fixed ("=r").
// TMA bulk LOADS (85x 256B per tile) + in-place register-staged transpose +
// TMA bulk store. No LDG on the hot path.
// Input:  [16, 255, 80, 80] fp32 (channel stride 6400)
// Output: [16, 19200, 85] fp32  (85 contiguous per cell)

#define NA      3
#define CH      85
#define HW      6400
#define WW      80
#define CELLS   64
#define THREADS 256
#define STRIDE  8.0f
#define TILE_BYTES (CELLS * CH * 4)   // 21,760

__device__ __forceinline__ float fsigmoid(float x) {
    float y;
    asm("tanh.approx.f32 %0, %1;" : "=f"(y) : "f"(0.5f * x));
    return fmaf(0.5f, y, 0.5f);
}

__device__ __forceinline__ uint32_t smem_u32(const void* p) {
    uint32_t a;
    asm("{ .reg .u64 t; cvta.to.shared.u64 t, %1; cvt.u32.u64 %0, t; }"
        : "=r"(a) : "l"(p));
    return a;
}

__global__ __launch_bounds__(THREADS, 5)
void yolo_head_kernel(const float* __restrict__ in,
                      const float* __restrict__ anchors,
                      float* __restrict__ out) {
    // One buffer, used twice: first [ch][cell] (in), then in-place [cell][ch] (out).
    __shared__ __align__(16) float s[CELLS * CH];        // 21,760 B
    __shared__ __align__(8)  unsigned long long mbar;

    const int groups = HW / CELLS;    // 100
    int bid   = blockIdx.x;
    int group = bid % groups;
    int a     = (bid / groups) % NA;
    int b     = bid / (NA * groups);
    int pos0  = group * CELLS;
    int tid   = threadIdx.x;

    const float* ib = in + (size_t)(b * NA + a) * (CH * HW) + pos0;
    uint32_t sbase = smem_u32(s);
    uint32_t mb    = smem_u32(&mbar);

    // ---- init barrier + set expected bytes (tid0, before any copy) ----
    if (tid == 0) {
        asm volatile("mbarrier.init.shared.b64 [%0], 1;" :: "r"(mb) : "memory");
        asm volatile("mbarrier.arrive.expect_tx.shared.b64 _, [%0], %1;"
                     :: "r"(mb), "r"(TILE_BYTES) : "memory");
    }
    __syncthreads();

    // ---- TMA loads: 85 x 256B contiguous channel rows -> smem [ch][cell] ----
    if (tid < CH) {
        uint64_t src = (uint64_t)(ib + (size_t)tid * HW);
        asm volatile(
            "cp.async.bulk.shared::cluster.global.mbarrier::complete_tx::bytes "
            "[%0], [%1], %2, [%3];"
            :: "r"(sbase + tid * (CELLS * 4)), "l"(src), "n"(CELLS * 4), "r"(mb)
            : "memory");
    }

    // ---- wait for the whole tile (acquire) ----
    {
        uint32_t done;
        asm volatile(
            "{\n\t.reg .pred p;\n\t"
            "mbarrier.try_wait.parity.acquire.cta.shared::cta.b64 p, [%1], 0;\n\t"
            "selp.b32 %0, 1, 0, p;\n\t}"
            : "=r"(done) : "r"(mb) : "memory");
        if (!done) {
            asm volatile(
                "{\n\t.reg .pred P1;\n\t"
                "W%=:\n\t"
                "mbarrier.try_wait.parity.acquire.cta.shared::cta.b64 P1, [%0], 0, 0x989680;\n\t"
                "@P1 bra.uni D%=;\n\t"
                "bra.uni W%=;\n\t"
                "D%=:\n\t}"
                :: "r"(mb) : "memory");
        }
    }

    // ---- compute: read smem [ch][cell], transform, hold ENTIRE tile in regs ----
    // 1360 float4 total = 5 x 256 + 80 remainder.
    float rv[5][4];
    float aw = anchors[2 * a + 0];
    float ah = anchors[2 * a + 1];
    #pragma unroll
    for (int p = 0; p < 5; p++) {
        int i = p * THREADS + tid;
        int c = i >> 4;                  // 0..79 (uniform per 16 lanes)
        int q = i & 15;
        float4 v = *(const float4*)(s + c * CELLS + 4 * q);
        float vv[4] = {v.x, v.y, v.z, v.w};
        #pragma unroll
        for (int k = 0; k < 4; k++) {
            int cell = 4 * q + k;
            float x = vv[k], t;
            if (c >= 4)      t = fsigmoid(x);
            else if (c == 0) t = (fsigmoid(x) + (float)((pos0 + cell) % WW)) * STRIDE;
            else if (c == 1) t = (fsigmoid(x) + (float)((pos0 + cell) / WW)) * STRIDE;
            else if (c == 2) t = __expf(fminf(fmaxf(x, -16.0f), 16.0f)) * aw;
            else             t = __expf(fminf(fmaxf(x, -16.0f), 16.0f)) * ah;
            rv[p][k] = t;
        }
    }
    float rem[4];
    if (tid < 80) {                      // channels 80..84: plain sigmoid
        int c = 80 + (tid >> 4);
        int q = tid & 15;
        float4 v = *(const float4*)(s + c * CELLS + 4 * q);
        rem[0] = fsigmoid(v.x); rem[1] = fsigmoid(v.y);
        rem[2] = fsigmoid(v.z); rem[3] = fsigmoid(v.w);
    }
    __syncthreads();                     // all reads done -> safe to overwrite

    // ---- in-place scatter to output layout [cell][ch] ----
    #pragma unroll
    for (int p = 0; p < 5; p++) {
        int i = p * THREADS + tid;
        int c = i >> 4;
        int q = i & 15;
        #pragma unroll
        for (int k = 0; k < 4; k++)
            s[(4 * q + k) * CH + c] = rv[p][k];
    }
    if (tid < 80) {
        int c = 80 + (tid >> 4);
        int q = tid & 15;
        #pragma unroll
        for (int k = 0; k < 4; k++)
            s[(4 * q + k) * CH + c] = rem[k];
    }
    __syncthreads();

    // ---- drain: single TMA bulk store; wait only for smem read-out ----
    if (tid == 0) {
        asm volatile("fence.proxy.async.shared::cta;" ::: "memory");
        uint64_t gaddr = (uint64_t)(out + (size_t)((b * NA + a) * HW + pos0) * CH);
        asm volatile(
            "cp.async.bulk.global.shared::cta.bulk_group [%0], [%1], %2;"
            :: "l"(gaddr), "r"(sbase), "n"(TILE_BYTES) : "memory");
        asm volatile("cp.async.bulk.commit_group;" ::: "memory");
        asm volatile("cp.async.bulk.wait_group.read 0;" ::: "memory");
    }
}

extern "C" void kernel_launch(void* const* d_in, const int* in_sizes, int n_in,
                              void* d_out, int out_size) {
    const float* in      = (const float*)d_in[0];
    const float* anchors = (const float*)d_in[1];
    float* out           = (float*)d_out;

    int grid = 16 * NA * (HW / CELLS);   // 4800 blocks
    yolo_head_kernel<<<grid, THREADS>>>(in, anchors, out);
}